// round 3
// baseline (speedup 1.0000x reference)
#include <cuda_runtime.h>
#include <cuda_bf16.h>
#include <stdint.h>

#define D_DIM     256
#define NROWS     16384
#define KCB       8192
#define M_TILE    128
#define N_CHUNK   128
#define NUM_CHUNKS 64
#define CAP       64
#define THRESH    8.0f
#define NUM_CTAS  128
#define THREADS   256
#define NELEM     4194304
#define ROWPITCH  528              // 256 bf16 + 8 pad bf16 = 528 bytes (16B aligned, conflict-free)

// ---------------- SMEM layout ----------------
#define OFF_A      0
#define OFF_B0     67584           // 128*528
#define OFF_B1     135168
#define OFF_CNORM  202752          // float[2][128]
#define OFF_WM     203776          // float[2][128]
#define OFF_RUNMIN 204800          // float[128]
#define OFF_CNT    205312          // int[128]
#define OFF_BEST   205824          // int[128]
#define OFF_CAND   206336          // u16[128][64]
#define SMEM_BYTES 222720

__device__ __align__(16) __nv_bfloat16 g_cb_bf16[KCB * D_DIM];
__device__ __align__(16) float  g_cnorm_f[KCB];
__device__ double g_cnorm_d[KCB];
__device__ double g_losspart[NUM_CTAS];

__device__ __forceinline__ uint32_t smem_u32(const void* p) {
    uint32_t a;
    asm("{ .reg .u64 t; cvta.to.shared.u64 t, %1; cvt.u32.u64 %0, t; }" : "=r"(a) : "l"(p));
    return a;
}
__device__ __forceinline__ void cp16(uint32_t dst, const void* src) {
    asm volatile("cp.async.cg.shared.global [%0], [%1], 16;" :: "r"(dst), "l"(src) : "memory");
}
#define CP_COMMIT() asm volatile("cp.async.commit_group;" ::: "memory")
#define CP_WAIT0()  asm volatile("cp.async.wait_group 0;" ::: "memory")

#define LDSM4(r0, r1, r2, r3, a) \
    asm volatile("ldmatrix.sync.aligned.m8n8.x4.shared.b16 {%0,%1,%2,%3}, [%4];" \
                 : "=r"(r0), "=r"(r1), "=r"(r2), "=r"(r3) : "r"(a))

#define MMA16816(d, a0, a1, a2, a3, b0, b1) \
    asm volatile("mma.sync.aligned.m16n8k16.row.col.f32.bf16.bf16.f32 " \
                 "{%0,%1,%2,%3}, {%4,%5,%6,%7}, {%8,%9}, {%0,%1,%2,%3};" \
                 : "+f"((d)[0]), "+f"((d)[1]), "+f"((d)[2]), "+f"((d)[3]) \
                 : "r"(a0), "r"(a1), "r"(a2), "r"(a3), "r"(b0), "r"(b1))

__device__ __forceinline__ uint32_t bf2u(__nv_bfloat162 h) {
    return *reinterpret_cast<uint32_t*>(&h);
}

// ======================= prep: bf16 codebook + norms =======================
__global__ void __launch_bounds__(256) vq_prep(const float* __restrict__ cb) {
    int row = blockIdx.x * 8 + (threadIdx.x >> 5);
    int l = threadIdx.x & 31;
    const float4* p = (const float4*)(cb + (size_t)row * D_DIM);
    float4 a = p[l], b = p[l + 32];
    uint2 ua, ub;
    ua.x = bf2u(__floats2bfloat162_rn(a.x, a.y));
    ua.y = bf2u(__floats2bfloat162_rn(a.z, a.w));
    ub.x = bf2u(__floats2bfloat162_rn(b.x, b.y));
    ub.y = bf2u(__floats2bfloat162_rn(b.z, b.w));
    uint2* dst = (uint2*)(g_cb_bf16 + (size_t)row * D_DIM);
    dst[l] = ua;
    dst[l + 32] = ub;
    double s = (double)a.x * a.x + (double)a.y * a.y + (double)a.z * a.z + (double)a.w * a.w
             + (double)b.x * b.x + (double)b.y * b.y + (double)b.z * b.z + (double)b.w * b.w;
    #pragma unroll
    for (int o = 16; o; o >>= 1) s += __shfl_xor_sync(0xffffffffu, s, o);
    if (l == 0) { g_cnorm_d[row] = s; g_cnorm_f[row] = (float)s; }
}

// =============== main: HMMA GEMM + argmin filter + rescore + gather ===============
__global__ void __launch_bounds__(THREADS, 1)
vq_main(const float* __restrict__ z, const float* __restrict__ cb,
        float* __restrict__ zq_out) {
    extern __shared__ char smem[];
    const uint32_t sbase = smem_u32(smem);
    const int tid = threadIdx.x;
    const int lane = tid & 31;
    const int w = tid >> 5;
    const int R0 = blockIdx.x * M_TILE;

    const int rb = (w >> 1) * 32;      // warp's 32-row block
    const int half = w & 1;            // warp's 64-col half of the chunk
    const int colbase = half * 64;

    // per-lane ldmatrix byte offsets
    const uint32_t aoff = sbase + OFF_A + (uint32_t)(rb + (lane & 15)) * ROWPITCH
                        + ((lane >> 4) ? 16u : 0u);
    const uint32_t boff = (uint32_t)(colbase + ((lane >> 4) & 1) * 8 + (lane & 7)) * ROWPITCH
                        + ((lane >> 3) & 1) * 16u;

    // ---- init shared state ----
    if (tid < 128) {
        ((float*)(smem + OFF_RUNMIN))[tid] = __int_as_float(0x7f800000);
        ((int*)(smem + OFF_CNT))[tid] = 0;
    }

    // ---- A tile: fp32 -> bf16, padded rows ----
    {
        const float* zb = z + (size_t)R0 * D_DIM;
        #pragma unroll 4
        for (int it = 0; it < 16; ++it) {
            int g = tid + it * THREADS;          // 4096 groups of 8 elems
            int row = g >> 5, col = (g & 31) * 8;
            const float4* p = (const float4*)(zb + row * D_DIM + col);
            float4 a = p[0], b = p[1];
            uint4 u;
            u.x = bf2u(__floats2bfloat162_rn(a.x, a.y));
            u.y = bf2u(__floats2bfloat162_rn(a.z, a.w));
            u.z = bf2u(__floats2bfloat162_rn(b.x, b.y));
            u.w = bf2u(__floats2bfloat162_rn(b.z, b.w));
            *(uint4*)(smem + OFF_A + row * ROWPITCH + col * 2) = u;
        }
    }
    // ---- chunk 0 via cp.async ----
    {
        const uint4* src = (const uint4*)(g_cb_bf16);
        uint32_t dstb = sbase + OFF_B0;
        #pragma unroll 4
        for (int it = 0; it < 16; ++it) {
            int g = tid + it * THREADS;
            cp16(dstb + (g >> 5) * ROWPITCH + (g & 31) * 16, src + g);
        }
        if (tid < 32) cp16(sbase + OFF_CNORM + tid * 16, g_cnorm_f + tid * 4);
        CP_COMMIT();
    }
    CP_WAIT0();
    __syncthreads();

    unsigned short* cand = (unsigned short*)(smem + OFF_CAND);
    int* cnt = (int*)(smem + OFF_CNT);
    float* runmin = (float*)(smem + OFF_RUNMIN);
    float* wm = (float*)(smem + OFF_WM);

    for (int c = 0; c < NUM_CHUNKS; ++c) {
        const int cur = c & 1;
        // prefetch next chunk into the other buffer
        if (c + 1 < NUM_CHUNKS) {
            const int nxt = cur ^ 1;
            const uint4* src = (const uint4*)(g_cb_bf16 + (size_t)(c + 1) * N_CHUNK * D_DIM);
            uint32_t dstb = sbase + (nxt ? OFF_B1 : OFF_B0);
            #pragma unroll 4
            for (int it = 0; it < 16; ++it) {
                int g = tid + it * THREADS;
                cp16(dstb + (g >> 5) * ROWPITCH + (g & 31) * 16, src + g);
            }
            if (tid < 32)
                cp16(sbase + OFF_CNORM + nxt * 512 + tid * 16,
                     g_cnorm_f + (c + 1) * 128 + tid * 4);
            CP_COMMIT();
        }

        // ---- GEMM: acc[rg][nt][4] = Z(32x256) . C^T(256x64) ----
        float acc[2][8][4];
        #pragma unroll
        for (int rg = 0; rg < 2; ++rg)
            #pragma unroll
            for (int nt = 0; nt < 8; ++nt)
                #pragma unroll
                for (int d = 0; d < 4; ++d) acc[rg][nt][d] = 0.0f;

        const uint32_t sB = sbase + (cur ? OFF_B1 : OFF_B0) + boff;
        #pragma unroll
        for (int ks = 0; ks < 16; ++ks) {
            uint32_t a0, a1, a2, a3, a4, a5, a6, a7;
            LDSM4(a0, a1, a2, a3, aoff + ks * 32);
            LDSM4(a4, a5, a6, a7, aoff + 16 * ROWPITCH + ks * 32);
            #pragma unroll
            for (int p = 0; p < 4; ++p) {
                uint32_t b0, b1, b2, b3;
                LDSM4(b0, b1, b2, b3, sB + p * (16 * ROWPITCH) + ks * 32);
                MMA16816(acc[0][2 * p],     a0, a1, a2, a3, b0, b1);
                MMA16816(acc[0][2 * p + 1], a0, a1, a2, a3, b2, b3);
                MMA16816(acc[1][2 * p],     a4, a5, a6, a7, b0, b1);
                MMA16816(acc[1][2 * p + 1], a4, a5, a6, a7, b2, b3);
            }
        }

        // ---- scores + per-row min ----
        const float* cns = (const float*)(smem + OFF_CNORM) + cur * 128;
        float m[4] = { __int_as_float(0x7f800000), __int_as_float(0x7f800000),
                       __int_as_float(0x7f800000), __int_as_float(0x7f800000) };
        #pragma unroll
        for (int rg = 0; rg < 2; ++rg)
            #pragma unroll
            for (int nt = 0; nt < 8; ++nt) {
                int c0 = colbase + nt * 8 + (lane & 3) * 2;
                float n0 = cns[c0], n1 = cns[c0 + 1];
                float s0 = fmaf(-2.0f, acc[rg][nt][0], n0);
                float s1 = fmaf(-2.0f, acc[rg][nt][1], n1);
                float s2 = fmaf(-2.0f, acc[rg][nt][2], n0);
                float s3 = fmaf(-2.0f, acc[rg][nt][3], n1);
                acc[rg][nt][0] = s0; acc[rg][nt][1] = s1;
                acc[rg][nt][2] = s2; acc[rg][nt][3] = s3;
                m[rg * 2]     = fminf(m[rg * 2],     fminf(s0, s1));
                m[rg * 2 + 1] = fminf(m[rg * 2 + 1], fminf(s2, s3));
            }
        #pragma unroll
        for (int j = 0; j < 4; ++j) {
            m[j] = fminf(m[j], __shfl_xor_sync(0xffffffffu, m[j], 1));
            m[j] = fminf(m[j], __shfl_xor_sync(0xffffffffu, m[j], 2));
        }
        if ((lane & 3) == 0) {
            #pragma unroll
            for (int j = 0; j < 4; ++j) {
                int row = rb + (j >> 1) * 16 + (j & 1) * 8 + (lane >> 2);
                wm[half * 128 + row] = m[j];
            }
        }
        __syncthreads();
        if (tid < 128)
            runmin[tid] = fminf(runmin[tid], fminf(wm[tid], wm[128 + tid]));
        __syncthreads();

        // ---- candidate append ----
        #pragma unroll
        for (int j = 0; j < 4; ++j) {
            int row = rb + (j >> 1) * 16 + (j & 1) * 8 + (lane >> 2);
            float thr = runmin[row] + THRESH;
            int rg = j >> 1, dh = (j & 1) * 2;
            #pragma unroll
            for (int nt = 0; nt < 8; ++nt) {
                int c0 = c * N_CHUNK + colbase + nt * 8 + (lane & 3) * 2;
                if (acc[rg][nt][dh] < thr) {
                    int ix = atomicAdd(&cnt[row], 1);
                    if (ix < CAP) cand[row * CAP + ix] = (unsigned short)c0;
                }
                if (acc[rg][nt][dh + 1] < thr) {
                    int ix = atomicAdd(&cnt[row], 1);
                    if (ix < CAP) cand[row * CAP + ix] = (unsigned short)(c0 + 1);
                }
            }
        }
        CP_WAIT0();
        __syncthreads();
    }

    // ---- exact fp64 rescore: warp w -> rows w*16 .. w*16+15 ----
    for (int rr = 0; rr < 16; ++rr) {
        int r = w * 16 + rr;
        int R = R0 + r;
        const float4* zp = (const float4*)(z + (size_t)R * D_DIM);
        float4 za = zp[lane], zb = zp[lane + 32];
        int rcnt = cnt[r];
        double best = 1e300;
        int bestj = 0;
        int total = (rcnt > CAP) ? KCB : rcnt;
        for (int ci = 0; ci < total; ++ci) {
            int j = (rcnt > CAP) ? ci : cand[r * CAP + ci];
            const float4* cp = (const float4*)(cb + (size_t)j * D_DIM);
            float4 ca = cp[lane], cv = cp[lane + 32];
            double d = (double)za.x * ca.x + (double)za.y * ca.y +
                       (double)za.z * ca.z + (double)za.w * ca.w +
                       (double)zb.x * cv.x + (double)zb.y * cv.y +
                       (double)zb.z * cv.z + (double)zb.w * cv.w;
            #pragma unroll
            for (int o = 16; o; o >>= 1) d += __shfl_xor_sync(0xffffffffu, d, o);
            double s = g_cnorm_d[j] - 2.0 * d;
            if (s < best) { best = s; bestj = j; }
        }
        if (lane == 0) ((int*)(smem + OFF_BEST))[r] = bestj;
    }
    __syncthreads();

    // ---- gather z_q + loss partial ----
    double lsum = 0.0;
    {
        const int sub = tid >> 6, l64 = tid & 63;
        for (int it = 0; it < 32; ++it) {
            int r = it * 4 + sub;
            int R = R0 + r;
            int j = ((const int*)(smem + OFF_BEST))[r];
            float4 q  = ((const float4*)(cb + (size_t)j * D_DIM))[l64];
            float4 ze = ((const float4*)(z  + (size_t)R * D_DIM))[l64];
            float* o = zq_out + (size_t)R * D_DIM + l64 * 4;   // base is odd-offset
            o[0] = q.x; o[1] = q.y; o[2] = q.z; o[3] = q.w;
            float dx = q.x - ze.x, dy = q.y - ze.y, dz = q.z - ze.z, dw = q.w - ze.w;
            lsum += (double)dx * dx + (double)dy * dy + (double)dz * dz + (double)dw * dw;
        }
    }
    __syncthreads();
    double* red = (double*)(smem + OFF_CAND);   // reuse candidate region
    red[tid] = lsum;
    __syncthreads();
    #pragma unroll
    for (int s = 128; s > 0; s >>= 1) {
        if (tid < s) red[tid] += red[tid + s];
        __syncthreads();
    }
    if (tid == 0) g_losspart[blockIdx.x] = red[0];
}

// ======================= loss reduction =======================
__global__ void vq_reduce(float* __restrict__ out_loss) {
    __shared__ double red[128];
    int t = threadIdx.x;
    red[t] = g_losspart[t];
    __syncthreads();
    #pragma unroll
    for (int k = 64; k > 0; k >>= 1) {
        if (t < k) red[t] += red[t + k];
        __syncthreads();
    }
    if (t == 0) out_loss[0] = (float)(2.0 * red[0] / (double)NELEM);
}

extern "C" void kernel_launch(void* const* d_in, const int* in_sizes, int n_in,
                              void* d_out, int out_size) {
    const float* z  = (const float*)d_in[0];
    const float* cb = (const float*)d_in[1];
    float* out = (float*)d_out;
    // output layout: [z_e (4194304) | loss (1) | z_q_st (4194304)]
    cudaFuncSetAttribute(vq_main, cudaFuncAttributeMaxDynamicSharedMemorySize, SMEM_BYTES);
    cudaMemcpyAsync(out, z, (size_t)NELEM * sizeof(float), cudaMemcpyDeviceToDevice);
    vq_prep<<<KCB / 8, 256>>>(cb);
    vq_main<<<NUM_CTAS, THREADS, SMEM_BYTES>>>(z, cb, out + NELEM + 1);
    vq_reduce<<<1, 128>>>(out + NELEM);
}